// round 11
// baseline (speedup 1.0000x reference)
#include <cuda_runtime.h>
#include <math.h>

#define NG        1536
#define WID       160
#define HEI       128
#define FX_       146.44f
#define FY_       146.44f
#define CX_       80.0f
#define CY_       64.0f
#define EPS2D_    0.3f
#define NEAR_     0.01f
#define FAR_      1e10f
#define LOG2E_    1.4426950408889634f
#define SKIP_THR  (-16.0f)             // log2 units; culled alpha <= 1.5e-5
#define FINF      __int_as_float(0x7f800000)
#define NPART     4                    // rank-scan split factor
#define CHUNK     (NG / NPART)         // 384 keys per scanning thread

#define NSEG2     32                   // render scan segments (one per warp)
#define SEGLEN2   (NG / NSEG2)         // 48
#define NPAIR     16                   // composite spans (2 segments each)

// ---------------- device scratch (sorted-by-depth gaussian data) ----------------
__device__ float4 g_s0[NG];            // u, v, axx, axy   (log2-space conic, opacity folded)
__device__ float4 g_s1[NG];            // ayy, lo, r, g
__device__ float4 g_scul[NG];          // u, v, rx, ry     (cull bbox)
__device__ float  g_sbl[NG];           // blue

__device__ __forceinline__ float fast_exp2(float x) {
    float r;
    asm("ex2.approx.f32 %0, %1;" : "=f"(r) : "f"(x));
    return r;
}

// ---------------- kernel 1: preprocess (warp 0) || split rank scan (warps 1-4) ----------------
// 48 blocks x 160 threads. Each block owns 32 gaussians. (unchanged from R9)
__global__ void __launch_bounds__(160) pre_rank_kernel(const float* __restrict__ means,
                                                       const float* __restrict__ quats,
                                                       const float* __restrict__ log_scales,
                                                       const float* __restrict__ opacity_logits,
                                                       const float* __restrict__ sh,
                                                       const float* __restrict__ c2w) {
    __shared__ float skey[NG];
    __shared__ int   srank[NPART][32];

    int tid  = threadIdx.x;
    int warp = tid >> 5;               // 0..4
    int lane = tid & 31;

    float W20 = -c2w[2], W21 = -c2w[6], W22 = -c2w[10];
    float tx0 = c2w[3], ty0 = c2w[7], tz0 = c2w[11];
    float tw2 = -(W20 * tx0 + W21 * ty0 + W22 * tz0);

    for (int i = tid; i < NG; i += 160) {
        float mx = means[3 * i + 0], my = means[3 * i + 1], mz = means[3 * i + 2];
        float d = W20 * mx + W21 * my + W22 * mz + tw2;
        bool mk = (d > NEAR_) && (d < FAR_);
        skey[i] = mk ? d : FINF;
    }
    __syncthreads();

    int n = blockIdx.x * 32 + lane;    // gaussian owned by this lane

    if (warp >= 1) {
        int part = warp - 1;
        float key = skey[n];
        const float4* sk4 = (const float4*)(skey + part * CHUNK);
        int jb0 = part * CHUNK;
        int r0 = 0, r1 = 0, r2 = 0, r3 = 0;
#pragma unroll 4
        for (int j4 = 0; j4 < CHUNK / 4; ++j4) {
            float4 v = sk4[j4];
            int jb = jb0 + j4 * 4;
            r0 += (v.x < key) || ((v.x == key) && (jb + 0 < n));
            r1 += (v.y < key) || ((v.y == key) && (jb + 1 < n));
            r2 += (v.z < key) || ((v.z == key) && (jb + 2 < n));
            r3 += (v.w < key) || ((v.w == key) && (jb + 3 < n));
        }
        srank[part][lane] = (r0 + r1) + (r2 + r3);
        __syncthreads();
        return;
    }

    // ================= warp 0: full preprocess for gaussian n =================
    const float sgn[3] = {1.f, -1.f, -1.f};
    float Wm[3][3];
#pragma unroll
    for (int i = 0; i < 3; ++i)
#pragma unroll
        for (int j = 0; j < 3; ++j)
            Wm[i][j] = c2w[j * 4 + i] * sgn[i];
    float tw[3];
#pragma unroll
    for (int i = 0; i < 3; ++i)
        tw[i] = -(Wm[i][0] * tx0 + Wm[i][1] * ty0 + Wm[i][2] * tz0);

    float mx = means[3 * n + 0], my = means[3 * n + 1], mz = means[3 * n + 2];
    float mc[3];
#pragma unroll
    for (int i = 0; i < 3; ++i)
        mc[i] = Wm[i][0] * mx + Wm[i][1] * my + Wm[i][2] * mz + tw[i];
    float depth = mc[2];
    bool mask = (depth > NEAR_) && (depth < FAR_);

    float dx = mx - tx0, dy = my - ty0, dz = mz - tz0;
    float rn = rsqrtf(dx * dx + dy * dy + dz * dz);
    float x = dx * rn, y = dy * rn, z = dz * rn;

    float basis[16];
    basis[0]  = 0.282095f;
    basis[1]  = -0.488603f * y;
    basis[2]  = 0.488603f * z;
    basis[3]  = -0.488603f * x;
    basis[4]  = 1.092548f * x * y;
    basis[5]  = -1.092548f * y * z;
    basis[6]  = 0.315392f * (3.f * z * z - 1.f);
    basis[7]  = -1.092548f * x * z;
    basis[8]  = 0.546274f * (x * x - y * y);
    basis[9]  = -0.590044f * y * (3.f * x * x - y * y);
    basis[10] = 2.890611f * x * y * z;
    basis[11] = -0.457046f * y * (5.f * z * z - 1.f);
    basis[12] = 0.373176f * z * (5.f * z * z - 3.f);
    basis[13] = -0.457046f * x * (5.f * z * z - 1.f);
    basis[14] = 1.445306f * z * (x * x - y * y);
    basis[15] = -0.590044f * x * (x * x - 3.f * y * y);

    float col[3] = {0.f, 0.f, 0.f};
    const float* shn = sh + n * 48;
#pragma unroll
    for (int k = 0; k < 16; ++k) {
        col[0] = fmaf(basis[k], shn[k * 3 + 0], col[0]);
        col[1] = fmaf(basis[k], shn[k * 3 + 1], col[1]);
        col[2] = fmaf(basis[k], shn[k * 3 + 2], col[2]);
    }
#pragma unroll
    for (int c = 0; c < 3; ++c) col[c] = fmaxf(col[c] + 0.5f, 0.f);

    float qw = quats[4 * n + 0], qx = quats[4 * n + 1], qy = quats[4 * n + 2], qz = quats[4 * n + 3];
    float qn = rsqrtf(qw * qw + qx * qx + qy * qy + qz * qz);
    qw *= qn; qx *= qn; qy *= qn; qz *= qn;
    float Rg[3][3];
    Rg[0][0] = 1.f - 2.f * (qy * qy + qz * qz);
    Rg[0][1] = 2.f * (qx * qy - qz * qw);
    Rg[0][2] = 2.f * (qx * qz + qy * qw);
    Rg[1][0] = 2.f * (qx * qy + qz * qw);
    Rg[1][1] = 1.f - 2.f * (qx * qx + qz * qz);
    Rg[1][2] = 2.f * (qy * qz - qx * qw);
    Rg[2][0] = 2.f * (qx * qz - qy * qw);
    Rg[2][1] = 2.f * (qy * qz + qx * qw);
    Rg[2][2] = 1.f - 2.f * (qx * qx + qy * qy);

    float e0 = expf(log_scales[3 * n + 0]);
    float e1 = expf(log_scales[3 * n + 1]);
    float e2 = expf(log_scales[3 * n + 2]);

    float Mc[3][3];
#pragma unroll
    for (int i = 0; i < 3; ++i) {
        float m0 = Wm[i][0] * Rg[0][0] + Wm[i][1] * Rg[1][0] + Wm[i][2] * Rg[2][0];
        float m1 = Wm[i][0] * Rg[0][1] + Wm[i][1] * Rg[1][1] + Wm[i][2] * Rg[2][1];
        float m2 = Wm[i][0] * Rg[0][2] + Wm[i][1] * Rg[1][2] + Wm[i][2] * Rg[2][2];
        Mc[i][0] = m0 * e0; Mc[i][1] = m1 * e1; Mc[i][2] = m2 * e2;
    }

    float tcx = mc[0], tcy = mc[1], tcz = mc[2];
    float rz = 1.f / tcz;
    float j00 = FX_ * rz, j02 = -FX_ * tcx * rz * rz;
    float j11 = FY_ * rz, j12 = -FY_ * tcy * rz * rz;

    float P0[3], P1[3];
#pragma unroll
    for (int j = 0; j < 3; ++j) {
        P0[j] = j00 * Mc[0][j] + j02 * Mc[2][j];
        P1[j] = j11 * Mc[1][j] + j12 * Mc[2][j];
    }
    float a = P0[0] * P0[0] + P0[1] * P0[1] + P0[2] * P0[2] + EPS2D_;
    float cc = P1[0] * P1[0] + P1[1] * P1[1] + P1[2] * P1[2] + EPS2D_;
    float b = P0[0] * P1[0] + P0[1] * P1[1] + P0[2] * P1[2];
    float det = a * cc - b * b;
    float inv = 1.f / det;
    float A = cc * inv, B = -b * inv, C = a * inv;

    float axx = -0.5f * LOG2E_ * A;
    float ayy = -0.5f * LOG2E_ * C;
    float axy = -LOG2E_ * B;

    float u = FX_ * tcx * rz + CX_;
    float v = FY_ * tcy * rz + CY_;

    float opac = 1.f / (1.f + expf(-opacity_logits[n]));
    float lo = log2f(opac);
    if (!mask) lo = -1e30f;

    float aq = -axx, bq = -axy, cq = -ayy;
    float t = lo - SKIP_THR;
    float rx = -1.f, ry = -1.f;
    if (t > 0.f) {
        float denom = 4.f * aq * cq - bq * bq;
        float rden = 4.f * t / denom;
        rx = sqrtf(cq * rden) + 1.0f;
        ry = sqrtf(aq * rden) + 1.0f;
    }

    __syncthreads();   // wait for scanning warps' partial ranks

    int rank = (srank[0][lane] + srank[1][lane]) + (srank[2][lane] + srank[3][lane]);

    g_s0[rank]   = make_float4(u, v, axx, axy);
    g_s1[rank]   = make_float4(ayy, lo, col[0], col[1]);
    g_scul[rank] = make_float4(u, v, rx, ry);
    g_sbl[rank]  = col[2];
}

// ---------------- kernel 2: 2-row bands, single block-wide scan, per-pair composite ----------------
// 320 blocks x 1024 threads. 32 warps each scan one 48-gaussian segment (block
// scans the list exactly ONCE). Then warp w composites segment pair (w>>1) for
// row (w&1): same per-warp composite load as R9, half the scan work globally.
__global__ void __launch_bounds__(1024, 2) render_kernel(float* __restrict__ out) {
    int lane = threadIdx.x;              // 0..31
    int w    = threadIdx.y;              // 0..31
    int bx = blockIdx.x % 5;
    int by = blockIdx.x / 5;
    int px0 = bx * 32;
    int py0 = by * 2;

    float fx0  = (float)px0;
    float fx1  = (float)(px0 + 31);
    float ycen = (float)py0 + 0.5f;      // band center

    __shared__ unsigned short slist[NSEG2][SEGLEN2];
    __shared__ float          sblue[NSEG2][SEGLEN2];
    __shared__ int            scnt[NSEG2];
    __shared__ float4         sred[NPAIR][2][32];

    // ---- phase 1: each warp culls its own 48-gaussian segment (one block-wide pass) ----
    int i0 = w * SEGLEN2;
    int cnt = 0;
#pragma unroll
    for (int r = 0; r < 2; ++r) {
        int idx = r * 32 + lane;
        bool valid = (idx < SEGLEN2);
        int g = i0 + (valid ? idx : 0);
        float4 cb = g_scul[g];           // u, v, rx, ry (coalesced)
        bool pass = valid &&
                    (fabsf(cb.y - ycen) < cb.w + 0.5f) &&
                    (cb.x + cb.z > fx0) && (cb.x - cb.z < fx1);
        unsigned m = __ballot_sync(0xffffffffu, pass);
        if (pass) {
            int slot = cnt + __popc(m & ((1u << lane) - 1u));
            slist[w][slot] = (unsigned short)g;
            sblue[w][slot] = g_sbl[g];
        }
        cnt += __popc(m);
    }
    if (lane == 0) scnt[w] = cnt;
    __syncthreads();

    // ---- phase 2: composite. warp w -> segment pair (w>>1), row (w&1). ----
    int pair = w >> 1;
    int row  = w & 1;
    float yc = (float)(py0 + row);
    float xc = (float)px0 + 15.5f;
    float lx = (float)lane - 15.5f;

    float T = 1.f, cr = 0.f, cg = 0.f, cbl = 0.f;
#pragma unroll
    for (int h = 0; h < 2; ++h) {
        int seg = pair * 2 + h;
        int c = scnt[seg];
        for (int j = 0; j < c; ++j) {
            int g = slist[seg][j];
            float4 a  = __ldg(&g_s0[g]);     // u, v, axx, axy  (broadcast)
            float4 b4 = __ldg(&g_s1[g]);     // ayy, lo, r, g
            float du = xc - a.x;             // uniform across warp
            float dv = yc - a.y;
            float tx = a.z * du;
            float s  = fmaf(a.w, dv, tx);
            float k0 = fmaf(du, s, b4.y);
            k0 = fmaf(b4.x * dv, dv, k0);
            float k1 = fmaf(a.w, dv, tx + tx);
            float p  = fmaf(fmaf(a.z, lx, k1), lx, k0);
            float alpha = fminf(fast_exp2(p), 0.999f);
            float wt = T * alpha;
            cr  = fmaf(wt, b4.z, cr);
            cg  = fmaf(wt, b4.w, cg);
            cbl = fmaf(wt, sblue[seg][j], cbl);
            T   = fmaf(-T, alpha, T);
        }
    }

    sred[pair][row][lane] = make_float4(T, cr, cg, cbl);
    __syncthreads();

    // ---- phase 3: ordered chain of the 16 pairs; warps 0/1 -> rows 0/1 ----
    if (w < 2) {
        float Tp = 1.f, R = 0.f, G = 0.f, B = 0.f;
#pragma unroll
        for (int k = 0; k < NPAIR; ++k) {
            float4 vv = sred[k][w][lane];
            R = fmaf(Tp, vv.y, R);
            G = fmaf(Tp, vv.z, G);
            B = fmaf(Tp, vv.w, B);
            Tp *= vv.x;
        }
        int pix = (py0 + w) * WID + px0 + lane;
        out[pix * 3 + 0] = R;
        out[pix * 3 + 1] = G;
        out[pix * 3 + 2] = B;
    }
}

// ---------------- launch ----------------
extern "C" void kernel_launch(void* const* d_in, const int* in_sizes, int n_in,
                              void* d_out, int out_size) {
    const float* means   = (const float*)d_in[0];
    const float* quats   = (const float*)d_in[1];
    const float* lscales = (const float*)d_in[2];
    const float* opl     = (const float*)d_in[3];
    const float* sh      = (const float*)d_in[4];
    const float* c2w     = (const float*)d_in[5];
    float* out = (float*)d_out;

    pre_rank_kernel<<<48, 160>>>(means, quats, lscales, opl, sh, c2w);
    render_kernel<<<5 * (HEI / 2), dim3(32, 32)>>>(out);
}

// round 12
// speedup vs baseline: 1.0960x; 1.0960x over previous
#include <cuda_runtime.h>
#include <math.h>

#define NG        1536
#define WID       160
#define HEI       128
#define FX_       146.44f
#define FY_       146.44f
#define CX_       80.0f
#define CY_       64.0f
#define EPS2D_    0.3f
#define NEAR_     0.01f
#define FAR_      1e10f
#define NSEG      16
#define SEGLEN    (NG / NSEG)          // 96
#define LOG2E_    1.4426950408889634f
#define SKIP_THR  (-16.0f)             // log2 units; culled alpha <= 1.5e-5
#define FINF      __int_as_float(0x7f800000)
#define NPART     4                    // rank-scan split factor
#define CHUNK     (NG / NPART)         // 384 keys per scanning thread

// ---------------- device scratch (sorted-by-depth gaussian data) ----------------
__device__ float4   g_s0[NG];          // u, v, axx, axy   (log2-space conic, opacity folded)
__device__ float4   g_s1[NG];          // ayy, lo, r, g
__device__ float    g_sbl[NG];         // blue
__device__ unsigned g_cw[NG];          // packed cull: bits[0:5] strip mask, [5:16] y0, [16:27] y1

__device__ __forceinline__ float fast_exp2(float x) {
    float r;
    asm("ex2.approx.f32 %0, %1;" : "=f"(r) : "f"(x));
    return r;
}

// ---------------- kernel 1: preprocess (warp 0) || split rank scan (warps 1-4) ----------------
// 48 blocks x 160 threads. Each block owns 32 gaussians.
__global__ void __launch_bounds__(160) pre_rank_kernel(const float* __restrict__ means,
                                                       const float* __restrict__ quats,
                                                       const float* __restrict__ log_scales,
                                                       const float* __restrict__ opacity_logits,
                                                       const float* __restrict__ sh,
                                                       const float* __restrict__ c2w) {
    __shared__ float skey[NG];
    __shared__ int   srank[NPART][32];

    int tid  = threadIdx.x;
    int warp = tid >> 5;               // 0..4
    int lane = tid & 31;

    // w2c depth row: Wm[2][j] = -c2w[j*4+2]
    float W20 = -c2w[2], W21 = -c2w[6], W22 = -c2w[10];
    float tx0 = c2w[3], ty0 = c2w[7], tz0 = c2w[11];
    float tw2 = -(W20 * tx0 + W21 * ty0 + W22 * tz0);

    for (int i = tid; i < NG; i += 160) {
        float mx = means[3 * i + 0], my = means[3 * i + 1], mz = means[3 * i + 2];
        float d = W20 * mx + W21 * my + W22 * mz + tw2;
        bool mk = (d > NEAR_) && (d < FAR_);
        skey[i] = mk ? d : FINF;
    }
    __syncthreads();

    int n = blockIdx.x * 32 + lane;    // gaussian owned by this lane

    if (warp >= 1) {
        // ---- split rank scan: warp w scans chunk (w-1) for gaussian n ----
        int part = warp - 1;
        float key = skey[n];
        const float4* sk4 = (const float4*)(skey + part * CHUNK);
        int jb0 = part * CHUNK;
        int r0 = 0, r1 = 0, r2 = 0, r3 = 0;
#pragma unroll 4
        for (int j4 = 0; j4 < CHUNK / 4; ++j4) {
            float4 v = sk4[j4];
            int jb = jb0 + j4 * 4;
            r0 += (v.x < key) || ((v.x == key) && (jb + 0 < n));
            r1 += (v.y < key) || ((v.y == key) && (jb + 1 < n));
            r2 += (v.z < key) || ((v.z == key) && (jb + 2 < n));
            r3 += (v.w < key) || ((v.w == key) && (jb + 3 < n));
        }
        srank[part][lane] = (r0 + r1) + (r2 + r3);
        __syncthreads();
        return;
    }

    // ================= warp 0: full preprocess for gaussian n =================
    const float sgn[3] = {1.f, -1.f, -1.f};
    float Wm[3][3];
#pragma unroll
    for (int i = 0; i < 3; ++i)
#pragma unroll
        for (int j = 0; j < 3; ++j)
            Wm[i][j] = c2w[j * 4 + i] * sgn[i];
    float tw[3];
#pragma unroll
    for (int i = 0; i < 3; ++i)
        tw[i] = -(Wm[i][0] * tx0 + Wm[i][1] * ty0 + Wm[i][2] * tz0);

    float mx = means[3 * n + 0], my = means[3 * n + 1], mz = means[3 * n + 2];
    float mc[3];
#pragma unroll
    for (int i = 0; i < 3; ++i)
        mc[i] = Wm[i][0] * mx + Wm[i][1] * my + Wm[i][2] * mz + tw[i];
    float depth = mc[2];
    bool mask = (depth > NEAR_) && (depth < FAR_);

    // view direction
    float dx = mx - tx0, dy = my - ty0, dz = mz - tz0;
    float rn = rsqrtf(dx * dx + dy * dy + dz * dz);
    float x = dx * rn, y = dy * rn, z = dz * rn;

    float basis[16];
    basis[0]  = 0.282095f;
    basis[1]  = -0.488603f * y;
    basis[2]  = 0.488603f * z;
    basis[3]  = -0.488603f * x;
    basis[4]  = 1.092548f * x * y;
    basis[5]  = -1.092548f * y * z;
    basis[6]  = 0.315392f * (3.f * z * z - 1.f);
    basis[7]  = -1.092548f * x * z;
    basis[8]  = 0.546274f * (x * x - y * y);
    basis[9]  = -0.590044f * y * (3.f * x * x - y * y);
    basis[10] = 2.890611f * x * y * z;
    basis[11] = -0.457046f * y * (5.f * z * z - 1.f);
    basis[12] = 0.373176f * z * (5.f * z * z - 3.f);
    basis[13] = -0.457046f * x * (5.f * z * z - 1.f);
    basis[14] = 1.445306f * z * (x * x - y * y);
    basis[15] = -0.590044f * x * (x * x - 3.f * y * y);

    float col[3] = {0.f, 0.f, 0.f};
    const float* shn = sh + n * 48;
#pragma unroll
    for (int k = 0; k < 16; ++k) {
        col[0] = fmaf(basis[k], shn[k * 3 + 0], col[0]);
        col[1] = fmaf(basis[k], shn[k * 3 + 1], col[1]);
        col[2] = fmaf(basis[k], shn[k * 3 + 2], col[2]);
    }
#pragma unroll
    for (int c = 0; c < 3; ++c) col[c] = fmaxf(col[c] + 0.5f, 0.f);

    float qw = quats[4 * n + 0], qx = quats[4 * n + 1], qy = quats[4 * n + 2], qz = quats[4 * n + 3];
    float qn = rsqrtf(qw * qw + qx * qx + qy * qy + qz * qz);
    qw *= qn; qx *= qn; qy *= qn; qz *= qn;
    float Rg[3][3];
    Rg[0][0] = 1.f - 2.f * (qy * qy + qz * qz);
    Rg[0][1] = 2.f * (qx * qy - qz * qw);
    Rg[0][2] = 2.f * (qx * qz + qy * qw);
    Rg[1][0] = 2.f * (qx * qy + qz * qw);
    Rg[1][1] = 1.f - 2.f * (qx * qx + qz * qz);
    Rg[1][2] = 2.f * (qy * qz - qx * qw);
    Rg[2][0] = 2.f * (qx * qz - qy * qw);
    Rg[2][1] = 2.f * (qy * qz + qx * qw);
    Rg[2][2] = 1.f - 2.f * (qx * qx + qy * qy);

    float e0 = expf(log_scales[3 * n + 0]);
    float e1 = expf(log_scales[3 * n + 1]);
    float e2 = expf(log_scales[3 * n + 2]);

    float Mc[3][3];
#pragma unroll
    for (int i = 0; i < 3; ++i) {
        float m0 = Wm[i][0] * Rg[0][0] + Wm[i][1] * Rg[1][0] + Wm[i][2] * Rg[2][0];
        float m1 = Wm[i][0] * Rg[0][1] + Wm[i][1] * Rg[1][1] + Wm[i][2] * Rg[2][1];
        float m2 = Wm[i][0] * Rg[0][2] + Wm[i][1] * Rg[1][2] + Wm[i][2] * Rg[2][2];
        Mc[i][0] = m0 * e0; Mc[i][1] = m1 * e1; Mc[i][2] = m2 * e2;
    }

    float tcx = mc[0], tcy = mc[1], tcz = mc[2];
    float rz = 1.f / tcz;
    float j00 = FX_ * rz, j02 = -FX_ * tcx * rz * rz;
    float j11 = FY_ * rz, j12 = -FY_ * tcy * rz * rz;

    float P0[3], P1[3];
#pragma unroll
    for (int j = 0; j < 3; ++j) {
        P0[j] = j00 * Mc[0][j] + j02 * Mc[2][j];
        P1[j] = j11 * Mc[1][j] + j12 * Mc[2][j];
    }
    float a = P0[0] * P0[0] + P0[1] * P0[1] + P0[2] * P0[2] + EPS2D_;
    float cc = P1[0] * P1[0] + P1[1] * P1[1] + P1[2] * P1[2] + EPS2D_;
    float b = P0[0] * P1[0] + P0[1] * P1[1] + P0[2] * P1[2];
    float det = a * cc - b * b;
    float inv = 1.f / det;
    float A = cc * inv, B = -b * inv, C = a * inv;

    float axx = -0.5f * LOG2E_ * A;
    float ayy = -0.5f * LOG2E_ * C;
    float axy = -LOG2E_ * B;

    float u = FX_ * tcx * rz + CX_;
    float v = FY_ * tcy * rz + CY_;

    float opac = 1.f / (1.f + expf(-opacity_logits[n]));
    float lo = log2f(opac);
    if (!mask) lo = -1e30f;

    // bbox of ellipse p = SKIP_THR -> packed cull word
    float aq = -axx, bq = -axy, cq = -ayy;
    float t = lo - SKIP_THR;
    unsigned cw = 0;
    if (t > 0.f) {
        float denom = 4.f * aq * cq - bq * bq;
        float rden = 4.f * t / denom;
        float rx = sqrtf(cq * rden) + 1.0f;
        float ry = sqrtf(aq * rden) + 1.0f;
        int y0i = (int)floorf(v - ry) + 1;     // smallest integer py with py > v-ry
        int y1i = (int)floorf(v + ry);         // superset-safe largest py with py < v+ry
        y0i = max(0, y0i);
        y1i = min(HEI - 1, y1i);
        if (y0i <= y1i) {
            unsigned smask = 0;
#pragma unroll
            for (int s = 0; s < 5; ++s) {
                float xs0 = (float)(s * 32);
                if ((u + rx > xs0) && (u - rx < xs0 + 31.f)) smask |= (1u << s);
            }
            cw = smask | ((unsigned)y0i << 5) | ((unsigned)y1i << 16);
        }
    }

    __syncthreads();   // wait for scanning warps' partial ranks

    int rank = (srank[0][lane] + srank[1][lane]) + (srank[2][lane] + srank[3][lane]);

    g_s0[rank]  = make_float4(u, v, axx, axy);
    g_s1[rank]  = make_float4(ayy, lo, col[0], col[1]);
    g_sbl[rank] = col[2];
    g_cw[rank]  = cw;
}

// ---------------- kernel 2: culled (packed-word), segmented per-pixel compositing ----------------
__global__ void __launch_bounds__(32 * NSEG, 4) render_kernel(float* __restrict__ out) {
    int lane = threadIdx.x;              // 0..31  -> pixel within 32-px row strip
    int seg  = threadIdx.y;              // 0..NSEG-1 -> gaussian segment
    int pixbase = blockIdx.x * 32;       // strips never cross rows: 160 = 5*32
    int px0 = pixbase % WID;
    int py  = pixbase / WID;
    int strip = px0 >> 5;                // 0..4

    float yc = (float)py;
    float xc = (float)px0 + 15.5f;
    float lx = (float)lane - 15.5f;

    __shared__ unsigned short slist[NSEG][SEGLEN];
    __shared__ float          sblue[NSEG][SEGLEN];
    __shared__ float4         sred[NSEG][32];

    // ---- scan & compact this warp's segment (coalesced LDG.32 on packed words) ----
    int i0 = seg * SEGLEN;
    int cnt = 0;
#pragma unroll
    for (int r = 0; r < SEGLEN / 32; ++r) {
        int g = i0 + r * 32 + lane;
        unsigned cw = g_cw[g];
        int y0 = (int)((cw >> 5) & 0x7FFu);
        int y1 = (int)(cw >> 16);
        bool pass = ((cw >> strip) & 1u) && (py >= y0) && (py <= y1);
        unsigned m = __ballot_sync(0xffffffffu, pass);
        if (pass) {
            int slot = cnt + __popc(m & ((1u << lane) - 1u));
            slist[seg][slot] = (unsigned short)g;
            sblue[seg][slot] = g_sbl[g];
        }
        cnt += __popc(m);
    }
    __syncwarp();

    // ---- composite survivors: branchless (underflowed exp2 -> alpha = 0 -> no-op) ----
    float T = 1.f, cr = 0.f, cg = 0.f, cbl = 0.f;
    for (int j = 0; j < cnt; ++j) {
        int g = slist[seg][j];
        float4 a  = __ldg(&g_s0[g]);     // u, v, axx, axy  (broadcast)
        float4 b4 = __ldg(&g_s1[g]);     // ayy, lo, r, g
        float du = xc - a.x;             // uniform across warp
        float dv = yc - a.y;
        float tx = a.z * du;
        float s  = fmaf(a.w, dv, tx);
        float k0 = fmaf(du, s, b4.y);
        k0 = fmaf(b4.x * dv, dv, k0);
        float k1 = fmaf(a.w, dv, tx + tx);
        float p  = fmaf(fmaf(a.z, lx, k1), lx, k0);
        float alpha = fminf(fast_exp2(p), 0.999f);
        float w = T * alpha;
        cr  = fmaf(w, b4.z, cr);
        cg  = fmaf(w, b4.w, cg);
        cbl = fmaf(w, sblue[seg][j], cbl);
        T   = fmaf(-T, alpha, T);
    }

    sred[seg][lane] = make_float4(T, cr, cg, cbl);
    __syncthreads();

    if (seg == 0) {
        float Tp = 1.f, R = 0.f, G = 0.f, B = 0.f;
#pragma unroll
        for (int k = 0; k < NSEG; ++k) {
            float4 vv = sred[k][lane];
            R = fmaf(Tp, vv.y, R);
            G = fmaf(Tp, vv.z, G);
            B = fmaf(Tp, vv.w, B);
            Tp *= vv.x;
        }
        int pix = pixbase + lane;
        out[pix * 3 + 0] = R;
        out[pix * 3 + 1] = G;
        out[pix * 3 + 2] = B;
    }
}

// ---------------- launch ----------------
extern "C" void kernel_launch(void* const* d_in, const int* in_sizes, int n_in,
                              void* d_out, int out_size) {
    const float* means   = (const float*)d_in[0];
    const float* quats   = (const float*)d_in[1];
    const float* lscales = (const float*)d_in[2];
    const float* opl     = (const float*)d_in[3];
    const float* sh      = (const float*)d_in[4];
    const float* c2w     = (const float*)d_in[5];
    float* out = (float*)d_out;

    pre_rank_kernel<<<48, 160>>>(means, quats, lscales, opl, sh, c2w);
    render_kernel<<<(WID * HEI) / 32, dim3(32, NSEG)>>>(out);
}

// round 13
// speedup vs baseline: 1.2794x; 1.1673x over previous
#include <cuda_runtime.h>
#include <math.h>

#define NG        1536
#define WID       160
#define HEI       128
#define FX_       146.44f
#define FY_       146.44f
#define CX_       80.0f
#define CY_       64.0f
#define EPS2D_    0.3f
#define NEAR_     0.01f
#define FAR_      1e10f
#define NSEG      16
#define SEGLEN    (NG / NSEG)          // 96
#define SCAP      48                   // staged survivors per segment (shared payload)
#define LOG2E_    1.4426950408889634f
#define SKIP_THR  (-16.0f)             // log2 units; culled alpha <= 1.5e-5
#define FINF      __int_as_float(0x7f800000)
#define NPART     4                    // rank-scan split factor
#define CHUNK     (NG / NPART)         // 384 keys per scanning thread

// ---------------- device scratch (sorted-by-depth gaussian data) ----------------
__device__ float4   g_s0[NG];          // u, v, axx, axy   (log2-space conic, opacity folded)
__device__ float4   g_s1[NG];          // ayy, lo, r, g
__device__ float    g_sbl[NG];         // blue
__device__ unsigned g_cw[NG];          // packed cull: bits[0:5] strip mask, [5:16] y0, [16:27] y1

__device__ __forceinline__ float fast_exp2(float x) {
    float r;
    asm("ex2.approx.f32 %0, %1;" : "=f"(r) : "f"(x));
    return r;
}

// ---------------- kernel 1: preprocess (warp 0) || split rank scan (warps 1-4) ----------------
// 48 blocks x 160 threads. Each block owns 32 gaussians.
__global__ void __launch_bounds__(160) pre_rank_kernel(const float* __restrict__ means,
                                                       const float* __restrict__ quats,
                                                       const float* __restrict__ log_scales,
                                                       const float* __restrict__ opacity_logits,
                                                       const float* __restrict__ sh,
                                                       const float* __restrict__ c2w) {
    __shared__ float skey[NG];
    __shared__ int   srank[NPART][32];

    int tid  = threadIdx.x;
    int warp = tid >> 5;               // 0..4
    int lane = tid & 31;

    // w2c depth row: Wm[2][j] = -c2w[j*4+2]
    float W20 = -c2w[2], W21 = -c2w[6], W22 = -c2w[10];
    float tx0 = c2w[3], ty0 = c2w[7], tz0 = c2w[11];
    float tw2 = -(W20 * tx0 + W21 * ty0 + W22 * tz0);

    for (int i = tid; i < NG; i += 160) {
        float mx = means[3 * i + 0], my = means[3 * i + 1], mz = means[3 * i + 2];
        float d = W20 * mx + W21 * my + W22 * mz + tw2;
        bool mk = (d > NEAR_) && (d < FAR_);
        skey[i] = mk ? d : FINF;
    }
    __syncthreads();

    int n = blockIdx.x * 32 + lane;    // gaussian owned by this lane

    if (warp >= 1) {
        // ---- split rank scan: warp w scans chunk (w-1) for gaussian n ----
        int part = warp - 1;
        float key = skey[n];
        const float4* sk4 = (const float4*)(skey + part * CHUNK);
        int jb0 = part * CHUNK;
        int r0 = 0, r1 = 0, r2 = 0, r3 = 0;
#pragma unroll 4
        for (int j4 = 0; j4 < CHUNK / 4; ++j4) {
            float4 v = sk4[j4];
            int jb = jb0 + j4 * 4;
            r0 += (v.x < key) || ((v.x == key) && (jb + 0 < n));
            r1 += (v.y < key) || ((v.y == key) && (jb + 1 < n));
            r2 += (v.z < key) || ((v.z == key) && (jb + 2 < n));
            r3 += (v.w < key) || ((v.w == key) && (jb + 3 < n));
        }
        srank[part][lane] = (r0 + r1) + (r2 + r3);
        __syncthreads();
        return;
    }

    // ================= warp 0: full preprocess for gaussian n =================
    const float sgn[3] = {1.f, -1.f, -1.f};
    float Wm[3][3];
#pragma unroll
    for (int i = 0; i < 3; ++i)
#pragma unroll
        for (int j = 0; j < 3; ++j)
            Wm[i][j] = c2w[j * 4 + i] * sgn[i];
    float tw[3];
#pragma unroll
    for (int i = 0; i < 3; ++i)
        tw[i] = -(Wm[i][0] * tx0 + Wm[i][1] * ty0 + Wm[i][2] * tz0);

    float mx = means[3 * n + 0], my = means[3 * n + 1], mz = means[3 * n + 2];
    float mc[3];
#pragma unroll
    for (int i = 0; i < 3; ++i)
        mc[i] = Wm[i][0] * mx + Wm[i][1] * my + Wm[i][2] * mz + tw[i];
    float depth = mc[2];
    bool mask = (depth > NEAR_) && (depth < FAR_);

    // view direction
    float dx = mx - tx0, dy = my - ty0, dz = mz - tz0;
    float rn = rsqrtf(dx * dx + dy * dy + dz * dz);
    float x = dx * rn, y = dy * rn, z = dz * rn;

    float basis[16];
    basis[0]  = 0.282095f;
    basis[1]  = -0.488603f * y;
    basis[2]  = 0.488603f * z;
    basis[3]  = -0.488603f * x;
    basis[4]  = 1.092548f * x * y;
    basis[5]  = -1.092548f * y * z;
    basis[6]  = 0.315392f * (3.f * z * z - 1.f);
    basis[7]  = -1.092548f * x * z;
    basis[8]  = 0.546274f * (x * x - y * y);
    basis[9]  = -0.590044f * y * (3.f * x * x - y * y);
    basis[10] = 2.890611f * x * y * z;
    basis[11] = -0.457046f * y * (5.f * z * z - 1.f);
    basis[12] = 0.373176f * z * (5.f * z * z - 3.f);
    basis[13] = -0.457046f * x * (5.f * z * z - 1.f);
    basis[14] = 1.445306f * z * (x * x - y * y);
    basis[15] = -0.590044f * x * (x * x - 3.f * y * y);

    float col[3] = {0.f, 0.f, 0.f};
    const float* shn = sh + n * 48;
#pragma unroll
    for (int k = 0; k < 16; ++k) {
        col[0] = fmaf(basis[k], shn[k * 3 + 0], col[0]);
        col[1] = fmaf(basis[k], shn[k * 3 + 1], col[1]);
        col[2] = fmaf(basis[k], shn[k * 3 + 2], col[2]);
    }
#pragma unroll
    for (int c = 0; c < 3; ++c) col[c] = fmaxf(col[c] + 0.5f, 0.f);

    float qw = quats[4 * n + 0], qx = quats[4 * n + 1], qy = quats[4 * n + 2], qz = quats[4 * n + 3];
    float qn = rsqrtf(qw * qw + qx * qx + qy * qy + qz * qz);
    qw *= qn; qx *= qn; qy *= qn; qz *= qn;
    float Rg[3][3];
    Rg[0][0] = 1.f - 2.f * (qy * qy + qz * qz);
    Rg[0][1] = 2.f * (qx * qy - qz * qw);
    Rg[0][2] = 2.f * (qx * qz + qy * qw);
    Rg[1][0] = 2.f * (qx * qy + qz * qw);
    Rg[1][1] = 1.f - 2.f * (qx * qx + qz * qz);
    Rg[1][2] = 2.f * (qy * qz - qx * qw);
    Rg[2][0] = 2.f * (qx * qz - qy * qw);
    Rg[2][1] = 2.f * (qy * qz + qx * qw);
    Rg[2][2] = 1.f - 2.f * (qx * qx + qy * qy);

    float e0 = expf(log_scales[3 * n + 0]);
    float e1 = expf(log_scales[3 * n + 1]);
    float e2 = expf(log_scales[3 * n + 2]);

    float Mc[3][3];
#pragma unroll
    for (int i = 0; i < 3; ++i) {
        float m0 = Wm[i][0] * Rg[0][0] + Wm[i][1] * Rg[1][0] + Wm[i][2] * Rg[2][0];
        float m1 = Wm[i][0] * Rg[0][1] + Wm[i][1] * Rg[1][1] + Wm[i][2] * Rg[2][1];
        float m2 = Wm[i][0] * Rg[0][2] + Wm[i][1] * Rg[1][2] + Wm[i][2] * Rg[2][2];
        Mc[i][0] = m0 * e0; Mc[i][1] = m1 * e1; Mc[i][2] = m2 * e2;
    }

    float tcx = mc[0], tcy = mc[1], tcz = mc[2];
    float rz = 1.f / tcz;
    float j00 = FX_ * rz, j02 = -FX_ * tcx * rz * rz;
    float j11 = FY_ * rz, j12 = -FY_ * tcy * rz * rz;

    float P0[3], P1[3];
#pragma unroll
    for (int j = 0; j < 3; ++j) {
        P0[j] = j00 * Mc[0][j] + j02 * Mc[2][j];
        P1[j] = j11 * Mc[1][j] + j12 * Mc[2][j];
    }
    float a = P0[0] * P0[0] + P0[1] * P0[1] + P0[2] * P0[2] + EPS2D_;
    float cc = P1[0] * P1[0] + P1[1] * P1[1] + P1[2] * P1[2] + EPS2D_;
    float b = P0[0] * P1[0] + P0[1] * P1[1] + P0[2] * P1[2];
    float det = a * cc - b * b;
    float inv = 1.f / det;
    float A = cc * inv, B = -b * inv, C = a * inv;

    float axx = -0.5f * LOG2E_ * A;
    float ayy = -0.5f * LOG2E_ * C;
    float axy = -LOG2E_ * B;

    float u = FX_ * tcx * rz + CX_;
    float v = FY_ * tcy * rz + CY_;

    float opac = 1.f / (1.f + expf(-opacity_logits[n]));
    float lo = log2f(opac);
    if (!mask) lo = -1e30f;

    // bbox of ellipse p = SKIP_THR -> packed cull word
    float aq = -axx, bq = -axy, cq = -ayy;
    float t = lo - SKIP_THR;
    unsigned cw = 0;
    if (t > 0.f) {
        float denom = 4.f * aq * cq - bq * bq;
        float rden = 4.f * t / denom;
        float rx = sqrtf(cq * rden) + 1.0f;
        float ry = sqrtf(aq * rden) + 1.0f;
        int y0i = (int)floorf(v - ry) + 1;
        int y1i = (int)floorf(v + ry);
        y0i = max(0, y0i);
        y1i = min(HEI - 1, y1i);
        if (y0i <= y1i) {
            unsigned smask = 0;
#pragma unroll
            for (int s = 0; s < 5; ++s) {
                float xs0 = (float)(s * 32);
                if ((u + rx > xs0) && (u - rx < xs0 + 31.f)) smask |= (1u << s);
            }
            cw = smask | ((unsigned)y0i << 5) | ((unsigned)y1i << 16);
        }
    }

    __syncthreads();   // wait for scanning warps' partial ranks

    int rank = (srank[0][lane] + srank[1][lane]) + (srank[2][lane] + srank[3][lane]);

    g_s0[rank]  = make_float4(u, v, axx, axy);
    g_s1[rank]  = make_float4(ayy, lo, col[0], col[1]);
    g_sbl[rank] = col[2];
    g_cw[rank]  = cw;
}

// ---------------- kernel 2: culled compositing with shared-staged payloads ----------------
__global__ void __launch_bounds__(32 * NSEG, 4) render_kernel(float* __restrict__ out) {
    int lane = threadIdx.x;              // 0..31  -> pixel within 32-px row strip
    int seg  = threadIdx.y;              // 0..NSEG-1 -> gaussian segment
    int pixbase = blockIdx.x * 32;       // strips never cross rows: 160 = 5*32
    int px0 = pixbase % WID;
    int py  = pixbase / WID;
    int strip = px0 >> 5;                // 0..4

    float yc = (float)py;
    float xc = (float)px0 + 15.5f;
    float lx = (float)lane - 15.5f;

    __shared__ unsigned short slist[NSEG][SEGLEN];
    __shared__ float4         sdat0[NSEG][SCAP];
    __shared__ float4         sdat1[NSEG][SCAP];
    __shared__ float          sblue[NSEG][SCAP];
    __shared__ float4         sred[NSEG][32];

    // ---- scan & compact; passing lanes stage full payloads into shared in parallel ----
    int i0 = seg * SEGLEN;
    int cnt = 0;
#pragma unroll
    for (int r = 0; r < SEGLEN / 32; ++r) {
        int g = i0 + r * 32 + lane;
        unsigned cw = g_cw[g];
        int y0 = (int)((cw >> 5) & 0x7FFu);
        int y1 = (int)(cw >> 16);
        bool pass = ((cw >> strip) & 1u) && (py >= y0) && (py <= y1);
        unsigned m = __ballot_sync(0xffffffffu, pass);
        if (pass) {
            int slot = cnt + __popc(m & ((1u << lane) - 1u));
            slist[seg][slot] = (unsigned short)g;
            if (slot < SCAP) {
                sdat0[seg][slot] = __ldg(&g_s0[g]);   // independent gathers, pipelined
                sdat1[seg][slot] = __ldg(&g_s1[g]);
                sblue[seg][slot] = __ldg(&g_sbl[g]);
            }
        }
        cnt += __popc(m);
    }
    __syncwarp();

    // ---- composite survivors from shared (branchless; LDS-only hot path) ----
    float T = 1.f, cr = 0.f, cg = 0.f, cbl = 0.f;
    int cstaged = min(cnt, SCAP);
    for (int j = 0; j < cstaged; ++j) {
        float4 a  = sdat0[seg][j];       // broadcast LDS
        float4 b4 = sdat1[seg][j];
        float du = xc - a.x;
        float dv = yc - a.y;
        float tx = a.z * du;
        float s  = fmaf(a.w, dv, tx);
        float k0 = fmaf(du, s, b4.y);
        k0 = fmaf(b4.x * dv, dv, k0);
        float k1 = fmaf(a.w, dv, tx + tx);
        float p  = fmaf(fmaf(a.z, lx, k1), lx, k0);
        float alpha = fminf(fast_exp2(p), 0.999f);
        float w = T * alpha;
        cr  = fmaf(w, b4.z, cr);
        cg  = fmaf(w, b4.w, cg);
        cbl = fmaf(w, sblue[seg][j], cbl);
        T   = fmaf(-T, alpha, T);
    }
    // rare overflow beyond staged capacity: fall back to global loads (order preserved)
    for (int j = SCAP; j < cnt; ++j) {
        int g = slist[seg][j];
        float4 a  = __ldg(&g_s0[g]);
        float4 b4 = __ldg(&g_s1[g]);
        float du = xc - a.x;
        float dv = yc - a.y;
        float tx = a.z * du;
        float s  = fmaf(a.w, dv, tx);
        float k0 = fmaf(du, s, b4.y);
        k0 = fmaf(b4.x * dv, dv, k0);
        float k1 = fmaf(a.w, dv, tx + tx);
        float p  = fmaf(fmaf(a.z, lx, k1), lx, k0);
        float alpha = fminf(fast_exp2(p), 0.999f);
        float w = T * alpha;
        cr  = fmaf(w, b4.z, cr);
        cg  = fmaf(w, b4.w, cg);
        cbl = fmaf(w, __ldg(&g_sbl[g]), cbl);
        T   = fmaf(-T, alpha, T);
    }

    sred[seg][lane] = make_float4(T, cr, cg, cbl);
    __syncthreads();

    if (seg == 0) {
        float Tp = 1.f, R = 0.f, G = 0.f, B = 0.f;
#pragma unroll
        for (int k = 0; k < NSEG; ++k) {
            float4 vv = sred[k][lane];
            R = fmaf(Tp, vv.y, R);
            G = fmaf(Tp, vv.z, G);
            B = fmaf(Tp, vv.w, B);
            Tp *= vv.x;
        }
        int pix = pixbase + lane;
        out[pix * 3 + 0] = R;
        out[pix * 3 + 1] = G;
        out[pix * 3 + 2] = B;
    }
}

// ---------------- launch ----------------
extern "C" void kernel_launch(void* const* d_in, const int* in_sizes, int n_in,
                              void* d_out, int out_size) {
    const float* means   = (const float*)d_in[0];
    const float* quats   = (const float*)d_in[1];
    const float* lscales = (const float*)d_in[2];
    const float* opl     = (const float*)d_in[3];
    const float* sh      = (const float*)d_in[4];
    const float* c2w     = (const float*)d_in[5];
    float* out = (float*)d_out;

    pre_rank_kernel<<<48, 160>>>(means, quats, lscales, opl, sh, c2w);
    render_kernel<<<(WID * HEI) / 32, dim3(32, NSEG)>>>(out);
}

// round 14
// speedup vs baseline: 1.3439x; 1.0505x over previous
#include <cuda_runtime.h>
#include <math.h>

#define NG        1536
#define WID       160
#define HEI       128
#define FX_       146.44f
#define FY_       146.44f
#define CX_       80.0f
#define CY_       64.0f
#define EPS2D_    0.3f
#define NEAR_     0.01f
#define FAR_      1e10f
#define NSEG      16
#define SEGLEN    (NG / NSEG)          // 96
#define SCAP      48                   // staged survivors per segment (shared payload)
#define LOG2E_    1.4426950408889634f
#define SKIP_THR  (-16.0f)             // log2 units; culled alpha <= 1.5e-5
#define FINF      __int_as_float(0x7f800000)
#define NPART     4                    // rank-scan split factor
#define CHUNK     (NG / NPART)         // 384 keys per scanning thread

// ---------------- device scratch (sorted-by-depth gaussian data) ----------------
__device__ float4   g_s0[NG];          // u, v, axx, axy   (log2-space conic, opacity folded)
__device__ float4   g_s1[NG];          // ayy, lo, r, g
__device__ float    g_sbl[NG];         // blue
__device__ unsigned g_cw[NG];          // packed cull: bits[0:5] strip mask, [5:16] y0, [16:27] y1

__device__ __forceinline__ float fast_exp2(float x) {
    float r;
    asm("ex2.approx.f32 %0, %1;" : "=f"(r) : "f"(x));
    return r;
}

// ---------------- kernel 1: preprocess (warp 0) || split rank scan (warps 1-4) ----------------
// 48 blocks x 160 threads. Each block owns 32 gaussians.
__global__ void __launch_bounds__(160) pre_rank_kernel(const float* __restrict__ means,
                                                       const float* __restrict__ quats,
                                                       const float* __restrict__ log_scales,
                                                       const float* __restrict__ opacity_logits,
                                                       const float* __restrict__ sh,
                                                       const float* __restrict__ c2w) {
    __shared__ float skey[NG];
    __shared__ int   srank[NPART][32];

    int tid  = threadIdx.x;
    int warp = tid >> 5;               // 0..4
    int lane = tid & 31;

    // w2c depth row: Wm[2][j] = -c2w[j*4+2]
    float W20 = -c2w[2], W21 = -c2w[6], W22 = -c2w[10];
    float tx0 = c2w[3], ty0 = c2w[7], tz0 = c2w[11];
    float tw2 = -(W20 * tx0 + W21 * ty0 + W22 * tz0);

    for (int i = tid; i < NG; i += 160) {
        float mx = means[3 * i + 0], my = means[3 * i + 1], mz = means[3 * i + 2];
        float d = W20 * mx + W21 * my + W22 * mz + tw2;
        bool mk = (d > NEAR_) && (d < FAR_);
        skey[i] = mk ? d : FINF;
    }
    __syncthreads();

    int n = blockIdx.x * 32 + lane;    // gaussian owned by this lane

    if (warp >= 1) {
        // ---- split rank scan: warp w scans chunk (w-1) for gaussian n ----
        int part = warp - 1;
        float key = skey[n];
        const float4* sk4 = (const float4*)(skey + part * CHUNK);
        int jb0 = part * CHUNK;
        int r0 = 0, r1 = 0, r2 = 0, r3 = 0;
#pragma unroll 4
        for (int j4 = 0; j4 < CHUNK / 4; ++j4) {
            float4 v = sk4[j4];
            int jb = jb0 + j4 * 4;
            r0 += (v.x < key) || ((v.x == key) && (jb + 0 < n));
            r1 += (v.y < key) || ((v.y == key) && (jb + 1 < n));
            r2 += (v.z < key) || ((v.z == key) && (jb + 2 < n));
            r3 += (v.w < key) || ((v.w == key) && (jb + 3 < n));
        }
        srank[part][lane] = (r0 + r1) + (r2 + r3);
        __syncthreads();
        return;
    }

    // ================= warp 0: full preprocess for gaussian n =================
    const float sgn[3] = {1.f, -1.f, -1.f};
    float Wm[3][3];
#pragma unroll
    for (int i = 0; i < 3; ++i)
#pragma unroll
        for (int j = 0; j < 3; ++j)
            Wm[i][j] = c2w[j * 4 + i] * sgn[i];
    float tw[3];
#pragma unroll
    for (int i = 0; i < 3; ++i)
        tw[i] = -(Wm[i][0] * tx0 + Wm[i][1] * ty0 + Wm[i][2] * tz0);

    float mx = means[3 * n + 0], my = means[3 * n + 1], mz = means[3 * n + 2];
    float mc[3];
#pragma unroll
    for (int i = 0; i < 3; ++i)
        mc[i] = Wm[i][0] * mx + Wm[i][1] * my + Wm[i][2] * mz + tw[i];
    float depth = mc[2];
    bool mask = (depth > NEAR_) && (depth < FAR_);

    // view direction
    float dx = mx - tx0, dy = my - ty0, dz = mz - tz0;
    float rn = rsqrtf(dx * dx + dy * dy + dz * dz);
    float x = dx * rn, y = dy * rn, z = dz * rn;

    float basis[16];
    basis[0]  = 0.282095f;
    basis[1]  = -0.488603f * y;
    basis[2]  = 0.488603f * z;
    basis[3]  = -0.488603f * x;
    basis[4]  = 1.092548f * x * y;
    basis[5]  = -1.092548f * y * z;
    basis[6]  = 0.315392f * (3.f * z * z - 1.f);
    basis[7]  = -1.092548f * x * z;
    basis[8]  = 0.546274f * (x * x - y * y);
    basis[9]  = -0.590044f * y * (3.f * x * x - y * y);
    basis[10] = 2.890611f * x * y * z;
    basis[11] = -0.457046f * y * (5.f * z * z - 1.f);
    basis[12] = 0.373176f * z * (5.f * z * z - 3.f);
    basis[13] = -0.457046f * x * (5.f * z * z - 1.f);
    basis[14] = 1.445306f * z * (x * x - y * y);
    basis[15] = -0.590044f * x * (x * x - 3.f * y * y);

    // vectorized SH load: 12 x float4 (sh + n*48 floats is 16B aligned)
    float shv[48];
    const float4* sh4 = (const float4*)(sh + n * 48);
#pragma unroll
    for (int i = 0; i < 12; ++i)
        ((float4*)shv)[i] = __ldg(&sh4[i]);

    float col[3] = {0.f, 0.f, 0.f};
#pragma unroll
    for (int k = 0; k < 16; ++k) {
        col[0] = fmaf(basis[k], shv[k * 3 + 0], col[0]);
        col[1] = fmaf(basis[k], shv[k * 3 + 1], col[1]);
        col[2] = fmaf(basis[k], shv[k * 3 + 2], col[2]);
    }
#pragma unroll
    for (int c = 0; c < 3; ++c) col[c] = fmaxf(col[c] + 0.5f, 0.f);

    float4 q4 = __ldg((const float4*)(quats + 4 * n));
    float qw = q4.x, qx = q4.y, qy = q4.z, qz = q4.w;
    float qn = rsqrtf(qw * qw + qx * qx + qy * qy + qz * qz);
    qw *= qn; qx *= qn; qy *= qn; qz *= qn;
    float Rg[3][3];
    Rg[0][0] = 1.f - 2.f * (qy * qy + qz * qz);
    Rg[0][1] = 2.f * (qx * qy - qz * qw);
    Rg[0][2] = 2.f * (qx * qz + qy * qw);
    Rg[1][0] = 2.f * (qx * qy + qz * qw);
    Rg[1][1] = 1.f - 2.f * (qx * qx + qz * qz);
    Rg[1][2] = 2.f * (qy * qz - qx * qw);
    Rg[2][0] = 2.f * (qx * qz - qy * qw);
    Rg[2][1] = 2.f * (qy * qz + qx * qw);
    Rg[2][2] = 1.f - 2.f * (qx * qx + qy * qy);

    float e0 = __expf(log_scales[3 * n + 0]);
    float e1 = __expf(log_scales[3 * n + 1]);
    float e2 = __expf(log_scales[3 * n + 2]);

    float Mc[3][3];
#pragma unroll
    for (int i = 0; i < 3; ++i) {
        float m0 = Wm[i][0] * Rg[0][0] + Wm[i][1] * Rg[1][0] + Wm[i][2] * Rg[2][0];
        float m1 = Wm[i][0] * Rg[0][1] + Wm[i][1] * Rg[1][1] + Wm[i][2] * Rg[2][1];
        float m2 = Wm[i][0] * Rg[0][2] + Wm[i][1] * Rg[1][2] + Wm[i][2] * Rg[2][2];
        Mc[i][0] = m0 * e0; Mc[i][1] = m1 * e1; Mc[i][2] = m2 * e2;
    }

    float tcx = mc[0], tcy = mc[1], tcz = mc[2];
    float rz = __fdividef(1.f, tcz);
    float j00 = FX_ * rz, j02 = -FX_ * tcx * rz * rz;
    float j11 = FY_ * rz, j12 = -FY_ * tcy * rz * rz;

    float P0[3], P1[3];
#pragma unroll
    for (int j = 0; j < 3; ++j) {
        P0[j] = j00 * Mc[0][j] + j02 * Mc[2][j];
        P1[j] = j11 * Mc[1][j] + j12 * Mc[2][j];
    }
    float a = P0[0] * P0[0] + P0[1] * P0[1] + P0[2] * P0[2] + EPS2D_;
    float cc = P1[0] * P1[0] + P1[1] * P1[1] + P1[2] * P1[2] + EPS2D_;
    float b = P0[0] * P1[0] + P0[1] * P1[1] + P0[2] * P1[2];
    float det = a * cc - b * b;
    float inv = __fdividef(1.f, det);
    float A = cc * inv, B = -b * inv, C = a * inv;

    float axx = -0.5f * LOG2E_ * A;
    float ayy = -0.5f * LOG2E_ * C;
    float axy = -LOG2E_ * B;

    float u = FX_ * tcx * rz + CX_;
    float v = FY_ * tcy * rz + CY_;

    // lo = log2(sigmoid(x)) = -log2(1 + exp(-x))   (MUFU chain)
    float lo = -__log2f(1.f + __expf(-opacity_logits[n]));
    if (!mask) lo = -1e30f;

    // bbox of ellipse p = SKIP_THR -> packed cull word
    float aq = -axx, bq = -axy, cq = -ayy;
    float t = lo - SKIP_THR;
    unsigned cw = 0;
    if (t > 0.f) {
        float denom = 4.f * aq * cq - bq * bq;
        float rden = __fdividef(4.f * t, denom);
        float rx = sqrtf(cq * rden) + 1.0f;
        float ry = sqrtf(aq * rden) + 1.0f;
        int y0i = (int)floorf(v - ry) + 1;
        int y1i = (int)floorf(v + ry);
        y0i = max(0, y0i);
        y1i = min(HEI - 1, y1i);
        if (y0i <= y1i) {
            unsigned smask = 0;
#pragma unroll
            for (int s = 0; s < 5; ++s) {
                float xs0 = (float)(s * 32);
                if ((u + rx > xs0) && (u - rx < xs0 + 31.f)) smask |= (1u << s);
            }
            cw = smask | ((unsigned)y0i << 5) | ((unsigned)y1i << 16);
        }
    }

    __syncthreads();   // wait for scanning warps' partial ranks

    int rank = (srank[0][lane] + srank[1][lane]) + (srank[2][lane] + srank[3][lane]);

    g_s0[rank]  = make_float4(u, v, axx, axy);
    g_s1[rank]  = make_float4(ayy, lo, col[0], col[1]);
    g_sbl[rank] = col[2];
    g_cw[rank]  = cw;
}

// ---------------- kernel 2: culled compositing with shared-staged payloads ----------------
__global__ void __launch_bounds__(32 * NSEG, 4) render_kernel(float* __restrict__ out) {
    int lane = threadIdx.x;              // 0..31  -> pixel within 32-px row strip
    int seg  = threadIdx.y;              // 0..NSEG-1 -> gaussian segment
    int pixbase = blockIdx.x * 32;       // strips never cross rows: 160 = 5*32
    int px0 = pixbase % WID;
    int py  = pixbase / WID;
    int strip = px0 >> 5;                // 0..4

    float yc = (float)py;
    float xc = (float)px0 + 15.5f;
    float lx = (float)lane - 15.5f;

    __shared__ unsigned short slist[NSEG][SEGLEN];
    __shared__ float4         sdat0[NSEG][SCAP];
    __shared__ float4         sdat1[NSEG][SCAP];
    __shared__ float          sblue[NSEG][SCAP];
    __shared__ float4         sred[NSEG][32];

    // ---- scan & compact; passing lanes stage full payloads into shared in parallel ----
    int i0 = seg * SEGLEN;
    int cnt = 0;
#pragma unroll
    for (int r = 0; r < SEGLEN / 32; ++r) {
        int g = i0 + r * 32 + lane;
        unsigned cw = g_cw[g];
        int y0 = (int)((cw >> 5) & 0x7FFu);
        int y1 = (int)(cw >> 16);
        bool pass = ((cw >> strip) & 1u) && (py >= y0) && (py <= y1);
        unsigned m = __ballot_sync(0xffffffffu, pass);
        if (pass) {
            int slot = cnt + __popc(m & ((1u << lane) - 1u));
            slist[seg][slot] = (unsigned short)g;
            if (slot < SCAP) {
                sdat0[seg][slot] = __ldg(&g_s0[g]);   // independent gathers, pipelined
                sdat1[seg][slot] = __ldg(&g_s1[g]);
                sblue[seg][slot] = __ldg(&g_sbl[g]);
            }
        }
        cnt += __popc(m);
    }
    __syncwarp();

    // ---- composite survivors from shared (branchless; LDS-only hot path) ----
    float T = 1.f, cr = 0.f, cg = 0.f, cbl = 0.f;
    int cstaged = min(cnt, SCAP);
    for (int j = 0; j < cstaged; ++j) {
        float4 a  = sdat0[seg][j];       // broadcast LDS
        float4 b4 = sdat1[seg][j];
        float du = xc - a.x;
        float dv = yc - a.y;
        float tx = a.z * du;
        float s  = fmaf(a.w, dv, tx);
        float k0 = fmaf(du, s, b4.y);
        k0 = fmaf(b4.x * dv, dv, k0);
        float k1 = fmaf(a.w, dv, tx + tx);
        float p  = fmaf(fmaf(a.z, lx, k1), lx, k0);
        float alpha = fminf(fast_exp2(p), 0.999f);
        float w = T * alpha;
        cr  = fmaf(w, b4.z, cr);
        cg  = fmaf(w, b4.w, cg);
        cbl = fmaf(w, sblue[seg][j], cbl);
        T   = fmaf(-T, alpha, T);
    }
    // rare overflow beyond staged capacity: fall back to global loads (order preserved)
    for (int j = SCAP; j < cnt; ++j) {
        int g = slist[seg][j];
        float4 a  = __ldg(&g_s0[g]);
        float4 b4 = __ldg(&g_s1[g]);
        float du = xc - a.x;
        float dv = yc - a.y;
        float tx = a.z * du;
        float s  = fmaf(a.w, dv, tx);
        float k0 = fmaf(du, s, b4.y);
        k0 = fmaf(b4.x * dv, dv, k0);
        float k1 = fmaf(a.w, dv, tx + tx);
        float p  = fmaf(fmaf(a.z, lx, k1), lx, k0);
        float alpha = fminf(fast_exp2(p), 0.999f);
        float w = T * alpha;
        cr  = fmaf(w, b4.z, cr);
        cg  = fmaf(w, b4.w, cg);
        cbl = fmaf(w, __ldg(&g_sbl[g]), cbl);
        T   = fmaf(-T, alpha, T);
    }

    sred[seg][lane] = make_float4(T, cr, cg, cbl);
    __syncthreads();

    if (seg == 0) {
        float Tp = 1.f, R = 0.f, G = 0.f, B = 0.f;
#pragma unroll
        for (int k = 0; k < NSEG; ++k) {
            float4 vv = sred[k][lane];
            R = fmaf(Tp, vv.y, R);
            G = fmaf(Tp, vv.z, G);
            B = fmaf(Tp, vv.w, B);
            Tp *= vv.x;
        }
        int pix = pixbase + lane;
        out[pix * 3 + 0] = R;
        out[pix * 3 + 1] = G;
        out[pix * 3 + 2] = B;
    }
}

// ---------------- launch ----------------
extern "C" void kernel_launch(void* const* d_in, const int* in_sizes, int n_in,
                              void* d_out, int out_size) {
    const float* means   = (const float*)d_in[0];
    const float* quats   = (const float*)d_in[1];
    const float* lscales = (const float*)d_in[2];
    const float* opl     = (const float*)d_in[3];
    const float* sh      = (const float*)d_in[4];
    const float* c2w     = (const float*)d_in[5];
    float* out = (float*)d_out;

    pre_rank_kernel<<<48, 160>>>(means, quats, lscales, opl, sh, c2w);
    render_kernel<<<(WID * HEI) / 32, dim3(32, NSEG)>>>(out);
}

// round 15
// speedup vs baseline: 1.3617x; 1.0133x over previous
#include <cuda_runtime.h>
#include <math.h>

#define NG        1536
#define WID       160
#define HEI       128
#define FX_       146.44f
#define FY_       146.44f
#define CX_       80.0f
#define CY_       64.0f
#define EPS2D_    0.3f
#define NEAR_     0.01f
#define FAR_      1e10f
#define NSEG      16
#define SEGLEN    (NG / NSEG)          // 96
#define SCAP      48                   // staged survivors per segment (shared payload)
#define LOG2E_    1.4426950408889634f
#define SKIP_THR  (-12.0f)             // log2 units; culled alpha <= 2.4e-4 at bbox edge
#define FINF      __int_as_float(0x7f800000)
#define NPART     4                    // rank-scan split factor
#define CHUNK     (NG / NPART)         // 384 keys per scanning thread

// ---------------- device scratch (sorted-by-depth gaussian data) ----------------
__device__ float4   g_s0[NG];          // u, v, axx, axy   (log2-space conic, opacity folded)
__device__ float4   g_s1[NG];          // ayy, lo, r, g
__device__ float    g_sbl[NG];         // blue
__device__ unsigned g_cw[NG];          // packed cull: bits[0:5] strip mask, [5:16] y0, [16:27] y1

__device__ __forceinline__ float fast_exp2(float x) {
    float r;
    asm("ex2.approx.f32 %0, %1;" : "=f"(r) : "f"(x));
    return r;
}

// ---------------- kernel 1: preprocess (warp 0) || split rank scan (warps 1-4) ----------------
// 48 blocks x 160 threads. Each block owns 32 gaussians.
__global__ void __launch_bounds__(160) pre_rank_kernel(const float* __restrict__ means,
                                                       const float* __restrict__ quats,
                                                       const float* __restrict__ log_scales,
                                                       const float* __restrict__ opacity_logits,
                                                       const float* __restrict__ sh,
                                                       const float* __restrict__ c2w) {
    __shared__ float smean[NG * 3];    // staged means (coalesced fill)
    __shared__ float skey[NG];
    __shared__ int   srank[NPART][32];

    int tid  = threadIdx.x;
    int warp = tid >> 5;               // 0..4
    int lane = tid & 31;

    // w2c depth row: Wm[2][j] = -c2w[j*4+2]
    float W20 = -c2w[2], W21 = -c2w[6], W22 = -c2w[10];
    float tx0 = c2w[3], ty0 = c2w[7], tz0 = c2w[11];
    float tw2 = -(W20 * tx0 + W21 * ty0 + W22 * tz0);

    // stage means into shared with coalesced float4 loads (NG*3 = 4608 floats = 1152 float4)
    const float4* m4 = (const float4*)means;
    for (int i = tid; i < NG * 3 / 4; i += 160)
        ((float4*)smean)[i] = __ldg(&m4[i]);
    __syncthreads();

    // depth keys from shared
    for (int i = tid; i < NG; i += 160) {
        float d = W20 * smean[3 * i + 0] + W21 * smean[3 * i + 1] + W22 * smean[3 * i + 2] + tw2;
        bool mk = (d > NEAR_) && (d < FAR_);
        skey[i] = mk ? d : FINF;
    }
    __syncthreads();

    int n = blockIdx.x * 32 + lane;    // gaussian owned by this lane

    if (warp >= 1) {
        // ---- split rank scan: warp w scans chunk (w-1) for gaussian n ----
        int part = warp - 1;
        float key = skey[n];
        const float4* sk4 = (const float4*)(skey + part * CHUNK);
        int jb0 = part * CHUNK;
        int r0 = 0, r1 = 0, r2 = 0, r3 = 0;
#pragma unroll 4
        for (int j4 = 0; j4 < CHUNK / 4; ++j4) {
            float4 v = sk4[j4];
            int jb = jb0 + j4 * 4;
            r0 += (v.x < key) || ((v.x == key) && (jb + 0 < n));
            r1 += (v.y < key) || ((v.y == key) && (jb + 1 < n));
            r2 += (v.z < key) || ((v.z == key) && (jb + 2 < n));
            r3 += (v.w < key) || ((v.w == key) && (jb + 3 < n));
        }
        srank[part][lane] = (r0 + r1) + (r2 + r3);
        __syncthreads();
        return;
    }

    // ================= warp 0: full preprocess for gaussian n =================
    const float sgn[3] = {1.f, -1.f, -1.f};
    float Wm[3][3];
#pragma unroll
    for (int i = 0; i < 3; ++i)
#pragma unroll
        for (int j = 0; j < 3; ++j)
            Wm[i][j] = c2w[j * 4 + i] * sgn[i];
    float tw[3];
#pragma unroll
    for (int i = 0; i < 3; ++i)
        tw[i] = -(Wm[i][0] * tx0 + Wm[i][1] * ty0 + Wm[i][2] * tz0);

    float mx = smean[3 * n + 0], my = smean[3 * n + 1], mz = smean[3 * n + 2];
    float mc[3];
#pragma unroll
    for (int i = 0; i < 3; ++i)
        mc[i] = Wm[i][0] * mx + Wm[i][1] * my + Wm[i][2] * mz + tw[i];
    float depth = mc[2];
    bool mask = (depth > NEAR_) && (depth < FAR_);

    // view direction
    float dx = mx - tx0, dy = my - ty0, dz = mz - tz0;
    float rn = rsqrtf(dx * dx + dy * dy + dz * dz);
    float x = dx * rn, y = dy * rn, z = dz * rn;

    float basis[16];
    basis[0]  = 0.282095f;
    basis[1]  = -0.488603f * y;
    basis[2]  = 0.488603f * z;
    basis[3]  = -0.488603f * x;
    basis[4]  = 1.092548f * x * y;
    basis[5]  = -1.092548f * y * z;
    basis[6]  = 0.315392f * (3.f * z * z - 1.f);
    basis[7]  = -1.092548f * x * z;
    basis[8]  = 0.546274f * (x * x - y * y);
    basis[9]  = -0.590044f * y * (3.f * x * x - y * y);
    basis[10] = 2.890611f * x * y * z;
    basis[11] = -0.457046f * y * (5.f * z * z - 1.f);
    basis[12] = 0.373176f * z * (5.f * z * z - 3.f);
    basis[13] = -0.457046f * x * (5.f * z * z - 1.f);
    basis[14] = 1.445306f * z * (x * x - y * y);
    basis[15] = -0.590044f * x * (x * x - 3.f * y * y);

    // vectorized SH load: 12 x float4 (sh + n*48 floats is 16B aligned)
    float shv[48];
    const float4* sh4 = (const float4*)(sh + n * 48);
#pragma unroll
    for (int i = 0; i < 12; ++i)
        ((float4*)shv)[i] = __ldg(&sh4[i]);

    float col[3] = {0.f, 0.f, 0.f};
#pragma unroll
    for (int k = 0; k < 16; ++k) {
        col[0] = fmaf(basis[k], shv[k * 3 + 0], col[0]);
        col[1] = fmaf(basis[k], shv[k * 3 + 1], col[1]);
        col[2] = fmaf(basis[k], shv[k * 3 + 2], col[2]);
    }
#pragma unroll
    for (int c = 0; c < 3; ++c) col[c] = fmaxf(col[c] + 0.5f, 0.f);

    float4 q4 = __ldg((const float4*)(quats + 4 * n));
    float qw = q4.x, qx = q4.y, qy = q4.z, qz = q4.w;
    float qn = rsqrtf(qw * qw + qx * qx + qy * qy + qz * qz);
    qw *= qn; qx *= qn; qy *= qn; qz *= qn;
    float Rg[3][3];
    Rg[0][0] = 1.f - 2.f * (qy * qy + qz * qz);
    Rg[0][1] = 2.f * (qx * qy - qz * qw);
    Rg[0][2] = 2.f * (qx * qz + qy * qw);
    Rg[1][0] = 2.f * (qx * qy + qz * qw);
    Rg[1][1] = 1.f - 2.f * (qx * qx + qz * qz);
    Rg[1][2] = 2.f * (qy * qz - qx * qw);
    Rg[2][0] = 2.f * (qx * qz - qy * qw);
    Rg[2][1] = 2.f * (qy * qz + qx * qw);
    Rg[2][2] = 1.f - 2.f * (qx * qx + qy * qy);

    float e0 = __expf(log_scales[3 * n + 0]);
    float e1 = __expf(log_scales[3 * n + 1]);
    float e2 = __expf(log_scales[3 * n + 2]);

    float Mc[3][3];
#pragma unroll
    for (int i = 0; i < 3; ++i) {
        float m0 = Wm[i][0] * Rg[0][0] + Wm[i][1] * Rg[1][0] + Wm[i][2] * Rg[2][0];
        float m1 = Wm[i][0] * Rg[0][1] + Wm[i][1] * Rg[1][1] + Wm[i][2] * Rg[2][1];
        float m2 = Wm[i][0] * Rg[0][2] + Wm[i][1] * Rg[1][2] + Wm[i][2] * Rg[2][2];
        Mc[i][0] = m0 * e0; Mc[i][1] = m1 * e1; Mc[i][2] = m2 * e2;
    }

    float tcx = mc[0], tcy = mc[1], tcz = mc[2];
    float rz = __fdividef(1.f, tcz);
    float j00 = FX_ * rz, j02 = -FX_ * tcx * rz * rz;
    float j11 = FY_ * rz, j12 = -FY_ * tcy * rz * rz;

    float P0[3], P1[3];
#pragma unroll
    for (int j = 0; j < 3; ++j) {
        P0[j] = j00 * Mc[0][j] + j02 * Mc[2][j];
        P1[j] = j11 * Mc[1][j] + j12 * Mc[2][j];
    }
    float a = P0[0] * P0[0] + P0[1] * P0[1] + P0[2] * P0[2] + EPS2D_;
    float cc = P1[0] * P1[0] + P1[1] * P1[1] + P1[2] * P1[2] + EPS2D_;
    float b = P0[0] * P1[0] + P0[1] * P1[1] + P0[2] * P1[2];
    float det = a * cc - b * b;
    float inv = __fdividef(1.f, det);
    float A = cc * inv, B = -b * inv, C = a * inv;

    float axx = -0.5f * LOG2E_ * A;
    float ayy = -0.5f * LOG2E_ * C;
    float axy = -LOG2E_ * B;

    float u = FX_ * tcx * rz + CX_;
    float v = FY_ * tcy * rz + CY_;

    // lo = log2(sigmoid(x)) = -log2(1 + exp(-x))   (MUFU chain)
    float lo = -__log2f(1.f + __expf(-opacity_logits[n]));
    if (!mask) lo = -1e30f;

    // bbox of ellipse p = SKIP_THR -> packed cull word
    float aq = -axx, bq = -axy, cq = -ayy;
    float t = lo - SKIP_THR;
    unsigned cw = 0;
    if (t > 0.f) {
        float denom = 4.f * aq * cq - bq * bq;
        float rden = __fdividef(4.f * t, denom);
        float rx = sqrtf(cq * rden) + 1.0f;
        float ry = sqrtf(aq * rden) + 1.0f;
        int y0i = (int)floorf(v - ry) + 1;
        int y1i = (int)floorf(v + ry);
        y0i = max(0, y0i);
        y1i = min(HEI - 1, y1i);
        if (y0i <= y1i) {
            unsigned smask = 0;
#pragma unroll
            for (int s = 0; s < 5; ++s) {
                float xs0 = (float)(s * 32);
                if ((u + rx > xs0) && (u - rx < xs0 + 31.f)) smask |= (1u << s);
            }
            cw = smask | ((unsigned)y0i << 5) | ((unsigned)y1i << 16);
        }
    }

    __syncthreads();   // wait for scanning warps' partial ranks

    int rank = (srank[0][lane] + srank[1][lane]) + (srank[2][lane] + srank[3][lane]);

    g_s0[rank]  = make_float4(u, v, axx, axy);
    g_s1[rank]  = make_float4(ayy, lo, col[0], col[1]);
    g_sbl[rank] = col[2];
    g_cw[rank]  = cw;
}

// ---------------- kernel 2: culled compositing with shared-staged payloads ----------------
__global__ void __launch_bounds__(32 * NSEG, 4) render_kernel(float* __restrict__ out) {
    int lane = threadIdx.x;              // 0..31  -> pixel within 32-px row strip
    int seg  = threadIdx.y;              // 0..NSEG-1 -> gaussian segment
    int pixbase = blockIdx.x * 32;       // strips never cross rows: 160 = 5*32
    int px0 = pixbase % WID;
    int py  = pixbase / WID;
    int strip = px0 >> 5;                // 0..4

    float yc = (float)py;
    float xc = (float)px0 + 15.5f;
    float lx = (float)lane - 15.5f;

    __shared__ unsigned short slist[NSEG][SEGLEN];
    __shared__ float4         sdat0[NSEG][SCAP];
    __shared__ float4         sdat1[NSEG][SCAP];
    __shared__ float          sblue[NSEG][SCAP];
    __shared__ float4         sred[NSEG][32];

    // ---- scan & compact; passing lanes stage full payloads into shared in parallel ----
    int i0 = seg * SEGLEN;
    int cnt = 0;
#pragma unroll
    for (int r = 0; r < SEGLEN / 32; ++r) {
        int g = i0 + r * 32 + lane;
        unsigned cw = g_cw[g];
        int y0 = (int)((cw >> 5) & 0x7FFu);
        int y1 = (int)(cw >> 16);
        bool pass = ((cw >> strip) & 1u) && (py >= y0) && (py <= y1);
        unsigned m = __ballot_sync(0xffffffffu, pass);
        if (pass) {
            int slot = cnt + __popc(m & ((1u << lane) - 1u));
            slist[seg][slot] = (unsigned short)g;
            if (slot < SCAP) {
                sdat0[seg][slot] = __ldg(&g_s0[g]);   // independent gathers, pipelined
                sdat1[seg][slot] = __ldg(&g_s1[g]);
                sblue[seg][slot] = __ldg(&g_sbl[g]);
            }
        }
        cnt += __popc(m);
    }
    __syncwarp();

    // ---- composite survivors from shared (branchless; LDS-only hot path) ----
    float T = 1.f, cr = 0.f, cg = 0.f, cbl = 0.f;
    int cstaged = min(cnt, SCAP);
    for (int j = 0; j < cstaged; ++j) {
        float4 a  = sdat0[seg][j];       // broadcast LDS
        float4 b4 = sdat1[seg][j];
        float du = xc - a.x;
        float dv = yc - a.y;
        float tx = a.z * du;
        float s  = fmaf(a.w, dv, tx);
        float k0 = fmaf(du, s, b4.y);
        k0 = fmaf(b4.x * dv, dv, k0);
        float k1 = fmaf(a.w, dv, tx + tx);
        float p  = fmaf(fmaf(a.z, lx, k1), lx, k0);
        float alpha = fminf(fast_exp2(p), 0.999f);
        float w = T * alpha;
        cr  = fmaf(w, b4.z, cr);
        cg  = fmaf(w, b4.w, cg);
        cbl = fmaf(w, sblue[seg][j], cbl);
        T   = fmaf(-T, alpha, T);
    }
    // rare overflow beyond staged capacity: fall back to global loads (order preserved)
    for (int j = SCAP; j < cnt; ++j) {
        int g = slist[seg][j];
        float4 a  = __ldg(&g_s0[g]);
        float4 b4 = __ldg(&g_s1[g]);
        float du = xc - a.x;
        float dv = yc - a.y;
        float tx = a.z * du;
        float s  = fmaf(a.w, dv, tx);
        float k0 = fmaf(du, s, b4.y);
        k0 = fmaf(b4.x * dv, dv, k0);
        float k1 = fmaf(a.w, dv, tx + tx);
        float p  = fmaf(fmaf(a.z, lx, k1), lx, k0);
        float alpha = fminf(fast_exp2(p), 0.999f);
        float w = T * alpha;
        cr  = fmaf(w, b4.z, cr);
        cg  = fmaf(w, b4.w, cg);
        cbl = fmaf(w, __ldg(&g_sbl[g]), cbl);
        T   = fmaf(-T, alpha, T);
    }

    sred[seg][lane] = make_float4(T, cr, cg, cbl);
    __syncthreads();

    if (seg == 0) {
        float Tp = 1.f, R = 0.f, G = 0.f, B = 0.f;
#pragma unroll
        for (int k = 0; k < NSEG; ++k) {
            float4 vv = sred[k][lane];
            R = fmaf(Tp, vv.y, R);
            G = fmaf(Tp, vv.z, G);
            B = fmaf(Tp, vv.w, B);
            Tp *= vv.x;
        }
        int pix = pixbase + lane;
        out[pix * 3 + 0] = R;
        out[pix * 3 + 1] = G;
        out[pix * 3 + 2] = B;
    }
}

// ---------------- launch ----------------
extern "C" void kernel_launch(void* const* d_in, const int* in_sizes, int n_in,
                              void* d_out, int out_size) {
    const float* means   = (const float*)d_in[0];
    const float* quats   = (const float*)d_in[1];
    const float* lscales = (const float*)d_in[2];
    const float* opl     = (const float*)d_in[3];
    const float* sh      = (const float*)d_in[4];
    const float* c2w     = (const float*)d_in[5];
    float* out = (float*)d_out;

    pre_rank_kernel<<<48, 160>>>(means, quats, lscales, opl, sh, c2w);
    render_kernel<<<(WID * HEI) / 32, dim3(32, NSEG)>>>(out);
}